// round 14
// baseline (speedup 1.0000x reference)
#include <cuda_runtime.h>
#include <cuda_fp16.h>
#include <math.h>
#include <stdint.h>

// Problem constants
#define Bb   2
#define Ss   2048
#define Dd   1024
#define NHh  16
#define HDd  64
#define MM   (Bb*Ss)
#define PLANE (Ss*Ss)
#define BSD  (Bb*Ss*Dd)

// ---------------- scratch (device globals) ----------------
__device__ __half g_Wq[Dd*Dd];     // permuted+transposed: [n'][k] fp16
__device__ __half g_Wk[Dd*Dd];
__device__ __half g_Wv[Dd*Dd];
__device__ __half g_Wo[Dd*Dd];     // row-permuted+transposed
__device__ float  g_bp[3*Dd];      // permuted biases (q,k,v)
__device__ __half g_Qh[BSD];       // [b,h,s,d] fp16
__device__ __half g_Kh[BSD];
__device__ __half g_Vh[BSD];
__device__ __half g_A[BSD];        // merged activations [b,s,h*64+d] fp16
__device__ __half g_P[134217728];  // normalized probs [b,h,l,n] fp16

// ---------------------------------------------------------------------------
// helpers
// ---------------------------------------------------------------------------
__device__ __forceinline__ void mma_f16(float* c, const uint32_t* a, const uint32_t* b) {
    asm volatile(
        "mma.sync.aligned.m16n8k16.row.col.f32.f16.f16.f32 "
        "{%0,%1,%2,%3}, {%4,%5,%6,%7}, {%8,%9}, {%0,%1,%2,%3};\n"
        : "+f"(c[0]), "+f"(c[1]), "+f"(c[2]), "+f"(c[3])
        : "r"(a[0]), "r"(a[1]), "r"(a[2]), "r"(a[3]), "r"(b[0]), "r"(b[1]));
}

union H8 { __half h[8]; uint4 u; };
union H16 { __half h[16]; uint4 u[2]; };

// ---------------------------------------------------------------------------
// perm_wT: Wt[h*64+d][r] = (half) W[r][d*16+h]   (for Wq/Wk/Wv)
// ---------------------------------------------------------------------------
__global__ __launch_bounds__(256) void perm_wT(
    const float* __restrict__ W, __half* __restrict__ Wt)
{
    __shared__ __half sm[16][1040];
    const int r0 = blockIdx.x * 16;
    const int tid = threadIdx.x;
#pragma unroll
    for (int it = 0; it < 16; ++it) {
        int ch = it * 256 + tid;
        int r = ch >> 8, c4 = (ch & 255) << 2;
        float4 v = *(const float4*)(W + (size_t)(r0 + r) * Dd + c4);
        *(__half2*)&sm[r][c4]     = __floats2half2_rn(v.x, v.y);
        *(__half2*)&sm[r][c4 + 2] = __floats2half2_rn(v.z, v.w);
    }
    __syncthreads();
#pragma unroll
    for (int i = 0; i < 4; ++i) {
        int cp = tid + i * 256;
        int src = ((cp & 63) << 4) + (cp >> 6);
        H16 t;
#pragma unroll
        for (int r = 0; r < 16; ++r) t.h[r] = sm[r][src];
        uint4* dst = (uint4*)(Wt + (size_t)cp * Dd + r0);
        dst[0] = t.u[0];
        dst[1] = t.u[1];
    }
}

// ---------------------------------------------------------------------------
// perm_woT: Wt[c][j] = (half) Wo[(j&63)*16 + (j>>6)][c]
// ---------------------------------------------------------------------------
__global__ __launch_bounds__(256) void perm_woT(
    const float* __restrict__ Wo, __half* __restrict__ Wt)
{
    __shared__ __half sm[1024][20];
    const int c0 = blockIdx.x * 16;
    const int tid = threadIdx.x;
#pragma unroll
    for (int it = 0; it < 16; ++it) {
        int ch = it * 256 + tid;
        int r = ch >> 2, c4 = (ch & 3) << 2;
        float4 v = *(const float4*)(Wo + (size_t)r * Dd + c0 + c4);
        *(__half2*)&sm[r][c4]     = __floats2half2_rn(v.x, v.y);
        *(__half2*)&sm[r][c4 + 2] = __floats2half2_rn(v.z, v.w);
    }
    __syncthreads();
    const int lc = tid >> 4;
    const int jc = tid & 15;
#pragma unroll
    for (int it = 0; it < 8; ++it) {
        int j0 = jc * 8 + it * 128;
        H8 t;
#pragma unroll
        for (int i = 0; i < 8; ++i) {
            int j = j0 + i;
            int src = ((j & 63) << 4) + (j >> 6);
            t.h[i] = sm[src][lc];
        }
        *(uint4*)(Wt + (size_t)(c0 + lc) * Dd + j0) = t.u;
    }
}

// perm_bias: bp[w*1024 + h*64+d] = b_w[d*16+h]
__global__ __launch_bounds__(256) void perm_bias(
    const float* __restrict__ b0, const float* __restrict__ b1,
    const float* __restrict__ b2, float* __restrict__ bp)
{
    int i = threadIdx.x + blockIdx.x * 256;
    int w = i >> 10, j = i & 1023;
    const float* src = (w == 0) ? b0 : ((w == 1) ? b1 : b2);
    bp[i] = src[((j & 63) << 4) + (j >> 6)];
}

// ---------------------------------------------------------------------------
// Projection GEMM (f16 mma, fp32 in): Oh[b,h,s,d] = (x @ W')[m, h*64+d] + bp
// ---------------------------------------------------------------------------
__global__ __launch_bounds__(256) void gemm_f16_headout(
    const float* __restrict__ A, const __half* __restrict__ Wt,
    const float* __restrict__ bp, __half* __restrict__ Oh)
{
    __shared__ __half As_[128][40];
    __shared__ __half Bs_[128][40];
    const int tid  = threadIdx.x;
    const int lane = tid & 31, w = tid >> 5;
    const int g = lane >> 2, tg = lane & 3;
    const int bm = blockIdx.y * 128, bn = blockIdx.x * 128;
    const int warpM = (w >> 2) * 64, warpN = (w & 3) * 32;

    float acc[4][4][4];
#pragma unroll
    for (int mt = 0; mt < 4; ++mt)
#pragma unroll
        for (int nt = 0; nt < 4; ++nt)
#pragma unroll
            for (int i = 0; i < 4; ++i) acc[mt][nt][i] = 0.f;

    float4 pa[4]; uint4 pw[2];
#pragma unroll
    for (int it = 0; it < 4; ++it) {
        int ch = tid + it * 256;
        int m = ch >> 3, kq = (ch & 7) << 2;
        pa[it] = *(const float4*)(A + (size_t)(bm + m) * Dd + kq);
    }
#pragma unroll
    for (int it = 0; it < 2; ++it) {
        int ch = tid + it * 256;
        int n = ch >> 2, kc = (ch & 3) << 3;
        pw[it] = *(const uint4*)(Wt + (size_t)(bn + n) * Dd + kc);
    }
#pragma unroll
    for (int it = 0; it < 4; ++it) {
        int ch = tid + it * 256;
        int m = ch >> 3, kq = (ch & 7) << 2;
        *(__half2*)&As_[m][kq]     = __floats2half2_rn(pa[it].x, pa[it].y);
        *(__half2*)&As_[m][kq + 2] = __floats2half2_rn(pa[it].z, pa[it].w);
    }
#pragma unroll
    for (int it = 0; it < 2; ++it) {
        int ch = tid + it * 256;
        int n = ch >> 2, kc = (ch & 3) << 3;
        *(uint4*)&Bs_[n][kc] = pw[it];
    }
    __syncthreads();

    for (int k0 = 32; k0 <= Dd; k0 += 32) {
        if (k0 < Dd) {
#pragma unroll
            for (int it = 0; it < 4; ++it) {
                int ch = tid + it * 256;
                int m = ch >> 3, kq = (ch & 7) << 2;
                pa[it] = *(const float4*)(A + (size_t)(bm + m) * Dd + k0 + kq);
            }
#pragma unroll
            for (int it = 0; it < 2; ++it) {
                int ch = tid + it * 256;
                int n = ch >> 2, kc = (ch & 3) << 3;
                pw[it] = *(const uint4*)(Wt + (size_t)(bn + n) * Dd + k0 + kc);
            }
        }
#pragma unroll
        for (int ks = 0; ks < 32; ks += 16) {
            uint32_t af[4][4], bf[4][2];
#pragma unroll
            for (int mt = 0; mt < 4; ++mt) {
                int r = warpM + mt * 16 + g;
                af[mt][0] = *(uint32_t*)&As_[r][ks + 2*tg];
                af[mt][1] = *(uint32_t*)&As_[r + 8][ks + 2*tg];
                af[mt][2] = *(uint32_t*)&As_[r][ks + 2*tg + 8];
                af[mt][3] = *(uint32_t*)&As_[r + 8][ks + 2*tg + 8];
            }
#pragma unroll
            for (int nt = 0; nt < 4; ++nt) {
                int c = warpN + nt * 8 + g;
                bf[nt][0] = *(uint32_t*)&Bs_[c][ks + 2*tg];
                bf[nt][1] = *(uint32_t*)&Bs_[c][ks + 2*tg + 8];
            }
#pragma unroll
            for (int mt = 0; mt < 4; ++mt)
#pragma unroll
                for (int nt = 0; nt < 4; ++nt)
                    mma_f16(acc[mt][nt], af[mt], bf[nt]);
        }
        if (k0 < Dd) {
            __syncthreads();
#pragma unroll
            for (int it = 0; it < 4; ++it) {
                int ch = tid + it * 256;
                int m = ch >> 3, kq = (ch & 7) << 2;
                *(__half2*)&As_[m][kq]     = __floats2half2_rn(pa[it].x, pa[it].y);
                *(__half2*)&As_[m][kq + 2] = __floats2half2_rn(pa[it].z, pa[it].w);
            }
#pragma unroll
            for (int it = 0; it < 2; ++it) {
                int ch = tid + it * 256;
                int n = ch >> 2, kc = (ch & 3) << 3;
                *(uint4*)&Bs_[n][kc] = pw[it];
            }
            __syncthreads();
        }
    }

#pragma unroll
    for (int mt = 0; mt < 4; ++mt)
#pragma unroll
        for (int nt = 0; nt < 4; ++nt) {
            int r0 = bm + warpM + mt * 16 + g;
            int c0 = bn + warpN + nt * 8 + 2 * tg;
            int b = r0 >> 11, s = r0 & 2047;
            int h = c0 >> 6, d = c0 & 63;
            float b0 = bp[c0], b1 = bp[c0 + 1];
            __half* dst = Oh + ((size_t)(b * 16 + h) * 2048 + s) * 64 + d;
            *(__half2*)(dst)          = __floats2half2_rn(acc[mt][nt][0] + b0, acc[mt][nt][1] + b1);
            *(__half2*)(dst + 8 * 64) = __floats2half2_rn(acc[mt][nt][2] + b0, acc[mt][nt][3] + b1);
        }
}

// ---------------------------------------------------------------------------
// Output projection (f16 x f16 -> fp32): out = g_A @ Wo' + bo
// ---------------------------------------------------------------------------
__global__ __launch_bounds__(256) void gemm_f16_bias(
    const __half* __restrict__ A, const __half* __restrict__ Wt,
    const float* __restrict__ bias, float* __restrict__ C)
{
    __shared__ __half As_[128][40];
    __shared__ __half Bs_[128][40];
    const int tid  = threadIdx.x;
    const int lane = tid & 31, w = tid >> 5;
    const int g = lane >> 2, tg = lane & 3;
    const int bm = blockIdx.y * 128, bn = blockIdx.x * 128;
    const int warpM = (w >> 2) * 64, warpN = (w & 3) * 32;

    float acc[4][4][4];
#pragma unroll
    for (int mt = 0; mt < 4; ++mt)
#pragma unroll
        for (int nt = 0; nt < 4; ++nt)
#pragma unroll
            for (int i = 0; i < 4; ++i) acc[mt][nt][i] = 0.f;

    uint4 pa[2], pw[2];
#pragma unroll
    for (int it = 0; it < 2; ++it) {
        int ch = tid + it * 256;
        int m = ch >> 2, kc = (ch & 3) << 3;
        pa[it] = *(const uint4*)(A + (size_t)(bm + m) * Dd + kc);
        pw[it] = *(const uint4*)(Wt + (size_t)(bn + m) * Dd + kc);
    }
#pragma unroll
    for (int it = 0; it < 2; ++it) {
        int ch = tid + it * 256;
        int m = ch >> 2, kc = (ch & 3) << 3;
        *(uint4*)&As_[m][kc] = pa[it];
        *(uint4*)&Bs_[m][kc] = pw[it];
    }
    __syncthreads();

    for (int k0 = 32; k0 <= Dd; k0 += 32) {
        if (k0 < Dd) {
#pragma unroll
            for (int it = 0; it < 2; ++it) {
                int ch = tid + it * 256;
                int m = ch >> 2, kc = (ch & 3) << 3;
                pa[it] = *(const uint4*)(A + (size_t)(bm + m) * Dd + k0 + kc);
                pw[it] = *(const uint4*)(Wt + (size_t)(bn + m) * Dd + k0 + kc);
            }
        }
#pragma unroll
        for (int ks = 0; ks < 32; ks += 16) {
            uint32_t af[4][4], bf[4][2];
#pragma unroll
            for (int mt = 0; mt < 4; ++mt) {
                int r = warpM + mt * 16 + g;
                af[mt][0] = *(uint32_t*)&As_[r][ks + 2*tg];
                af[mt][1] = *(uint32_t*)&As_[r + 8][ks + 2*tg];
                af[mt][2] = *(uint32_t*)&As_[r][ks + 2*tg + 8];
                af[mt][3] = *(uint32_t*)&As_[r + 8][ks + 2*tg + 8];
            }
#pragma unroll
            for (int nt = 0; nt < 4; ++nt) {
                int c = warpN + nt * 8 + g;
                bf[nt][0] = *(uint32_t*)&Bs_[c][ks + 2*tg];
                bf[nt][1] = *(uint32_t*)&Bs_[c][ks + 2*tg + 8];
            }
#pragma unroll
            for (int mt = 0; mt < 4; ++mt)
#pragma unroll
                for (int nt = 0; nt < 4; ++nt)
                    mma_f16(acc[mt][nt], af[mt], bf[nt]);
        }
        if (k0 < Dd) {
            __syncthreads();
#pragma unroll
            for (int it = 0; it < 2; ++it) {
                int ch = tid + it * 256;
                int m = ch >> 2, kc = (ch & 3) << 3;
                *(uint4*)&As_[m][kc] = pa[it];
                *(uint4*)&Bs_[m][kc] = pw[it];
            }
            __syncthreads();
        }
    }
#pragma unroll
    for (int mt = 0; mt < 4; ++mt)
#pragma unroll
        for (int nt = 0; nt < 4; ++nt) {
            int r0 = bm + warpM + mt * 16 + g;
            int c0 = bn + warpN + nt * 8 + 2 * tg;
            float b0 = bias[c0], b1 = bias[c0 + 1];
            float2 v0 = {acc[mt][nt][0] + b0, acc[mt][nt][1] + b1};
            float2 v1 = {acc[mt][nt][2] + b0, acc[mt][nt][3] + b1};
            *(float2*)(C + (size_t)r0 * Dd + c0) = v0;
            *(float2*)(C + (size_t)(r0 + 8) * Dd + c0) = v1;
        }
}

// ---------------------------------------------------------------------------
// FUSED scores + head-softmax, smem-resident score cube.
// Block: 32(l) x 64(n), 16 heads sequential. 8 warps (2l x 4n), warp 16x16.
// Per-head acc[2][4] only (8 regs). Scores cube Sc[16][32][68] fp32 in smem.
// Phase A: per-position softmax over h from smem -> probs (64B chunks) +
//          normalized values back into smem.
// Phase B: per-head coalesced fp16 stores to g_P planes.
// Dynamic smem: 16*32*68*4 + 32*72*2 + 64*72*2 = 153088 B.
// ---------------------------------------------------------------------------
#define SC_H (32*68)
#define FUSED_SMEM (16*32*68*4 + 32*72*2 + 64*72*2)

__global__ __launch_bounds__(256) void fused_scores_softmax(float* __restrict__ probs)
{
    extern __shared__ char dynsm[];
    float*  Sc  = (float*)dynsm;                         // [16][32][68]
    __half* Qs  = (__half*)(dynsm + 16*32*68*4);         // [32][72]
    __half* Ks  = (__half*)(dynsm + 16*32*68*4 + 32*72*2); // [64][72]

    const int tid  = threadIdx.x;
    const int lane = tid & 31, w = tid >> 5;
    const int g = lane >> 2, tg = lane & 3;
    const int b  = blockIdx.z;
    const int bm = blockIdx.y * 32;   // l
    const int bn = blockIdx.x * 64;   // n
    const int warpM = (w >> 2) * 16;  // 2 warps over l
    const int warpN = (w & 3) * 16;   // 4 warps over n

    // load indices
    const int qr = tid >> 3, qc = (tid & 7) << 3;        // Q: 32x64 -> 1 uint4/thread

    const __half* Qbase = g_Qh + (size_t)(b * 16) * (Ss * HDd);
    const __half* Kbase = g_Kh + (size_t)(b * 16) * (Ss * HDd);

    uint4 pq, pk[2];
    // preload head 0
    pq = *(const uint4*)(Qbase + (size_t)(bm + qr) * HDd + qc);
#pragma unroll
    for (int it = 0; it < 2; ++it) {
        int ch = tid + it * 256;
        int r = ch >> 3, c = (ch & 7) << 3;
        pk[it] = *(const uint4*)(Kbase + (size_t)(bn + r) * HDd + c);
    }

#pragma unroll 1
    for (int h = 0; h < 16; ++h) {
        // store current head's tiles
        *(uint4*)&Qs[qr * 72 + qc] = pq;
#pragma unroll
        for (int it = 0; it < 2; ++it) {
            int ch = tid + it * 256;
            int r = ch >> 3, c = (ch & 7) << 3;
            *(uint4*)&Ks[r * 72 + c] = pk[it];
        }
        __syncthreads();

        // prefetch next head
        if (h < 15) {
            const __half* Qn = Qbase + (size_t)(h + 1) * (Ss * HDd);
            const __half* Kn = Kbase + (size_t)(h + 1) * (Ss * HDd);
            pq = *(const uint4*)(Qn + (size_t)(bm + qr) * HDd + qc);
#pragma unroll
            for (int it = 0; it < 2; ++it) {
                int ch = tid + it * 256;
                int r = ch >> 3, c = (ch & 7) << 3;
                pk[it] = *(const uint4*)(Kn + (size_t)(bn + r) * HDd + c);
            }
        }

        float acc[2][4];
#pragma unroll
        for (int nt = 0; nt < 2; ++nt)
#pragma unroll
            for (int i = 0; i < 4; ++i) acc[nt][i] = 0.f;

#pragma unroll
        for (int ks = 0; ks < 64; ks += 16) {
            uint32_t af[4];
            af[0] = *(uint32_t*)&Qs[(warpM + g) * 72 + ks + 2*tg];
            af[1] = *(uint32_t*)&Qs[(warpM + g + 8) * 72 + ks + 2*tg];
            af[2] = *(uint32_t*)&Qs[(warpM + g) * 72 + ks + 2*tg + 8];
            af[3] = *(uint32_t*)&Qs[(warpM + g + 8) * 72 + ks + 2*tg + 8];
#pragma unroll
            for (int nt = 0; nt < 2; ++nt) {
                uint32_t bf[2];
                int c = warpN + nt * 8 + g;
                bf[0] = *(uint32_t*)&Ks[c * 72 + ks + 2*tg];
                bf[1] = *(uint32_t*)&Ks[c * 72 + ks + 2*tg + 8];
                mma_f16(acc[nt], af, bf);
            }
        }

        // dump scaled scores to smem cube
        float* Sch = Sc + h * SC_H;
#pragma unroll
        for (int nt = 0; nt < 2; ++nt) {
            int n2 = warpN + nt * 8 + 2 * tg;
            float2 v0 = {0.125f * acc[nt][0], 0.125f * acc[nt][1]};
            float2 v1 = {0.125f * acc[nt][2], 0.125f * acc[nt][3]};
            *(float2*)&Sch[(warpM + g) * 68 + n2]     = v0;
            *(float2*)&Sch[(warpM + g + 8) * 68 + n2] = v1;
        }
        __syncthreads();
    }

    // ---- Phase A: softmax over h. Thread owns l = tid>>3, n = (tid&7)*8 .. +7
    const int sl = tid >> 3;
    const int sn0 = (tid & 7) << 3;
    {
        float* base = Sc + sl * 68 + sn0;
        float* po_row = probs + ((size_t)((b * 2048 + bm + sl) * 2048 + bn + sn0)) * 16;
#pragma unroll
        for (int j = 0; j < 8; ++j) {
            float* p = base + j;
            float s[16];
#pragma unroll
            for (int h = 0; h < 16; ++h) s[h] = p[h * SC_H];
            float m = s[0];
#pragma unroll
            for (int h = 1; h < 16; ++h) m = fmaxf(m, s[h]);
            float sum = 0.f;
#pragma unroll
            for (int h = 0; h < 16; ++h) { s[h] = __expf(s[h] - m); sum += s[h]; }
            float r = 1.0f / sum;
            float* po = po_row + (size_t)j * 16;
#pragma unroll
            for (int h4 = 0; h4 < 16; h4 += 4) {
                float4 o = {s[h4]*r, s[h4+1]*r, s[h4+2]*r, s[h4+3]*r};
                *(float4*)(po + h4) = o;
            }
#pragma unroll
            for (int h = 0; h < 16; ++h) p[h * SC_H] = s[h] * r;
        }
    }
    // no sync needed: phase B reads only this thread's own positions

    // ---- Phase B: per-head coalesced fp16 stores to g_P
    {
        size_t prow = (size_t)(bm + sl) * Ss + bn + sn0;
#pragma unroll
        for (int h = 0; h < 16; ++h) {
            float* p = Sc + h * SC_H + sl * 68 + sn0;
            float4 a = *(float4*)(p);
            float4 c = *(float4*)(p + 4);
            H8 t;
            *(__half2*)&t.h[0] = __floats2half2_rn(a.x, a.y);
            *(__half2*)&t.h[2] = __floats2half2_rn(a.z, a.w);
            *(__half2*)&t.h[4] = __floats2half2_rn(c.x, c.y);
            *(__half2*)&t.h[6] = __floats2half2_rn(c.z, c.w);
            *(uint4*)(g_P + (size_t)(b * 16 + h) * PLANE + prow) = t.u;
        }
    }
}

// ---------------------------------------------------------------------------
// Attn*V (f16): per plane z: O[l,d] = sum_n P[l,n] * V[n,d]
// ---------------------------------------------------------------------------
__global__ __launch_bounds__(256) void attnv_f16()
{
    __shared__ __half Ps_[128][40];
    __shared__ __half Vs_[64][40];
    const int tid  = threadIdx.x;
    const int lane = tid & 31, w = tid >> 5;
    const int g = lane >> 2, tg = lane & 3;
    const int z  = blockIdx.y;
    const int bm = blockIdx.x * 128;
    const int warpM = (w >> 1) * 32, warpN = (w & 1) * 32;
    const __half* P = g_P + (size_t)z * PLANE;
    const __half* V = g_Vh + (size_t)z * (Ss*HDd);
    const int bz = z >> 4, hz = z & 15;
    __half* O = g_A + ((size_t)bz * 2048) * 1024 + hz * 64;

    float acc[2][4][4];
#pragma unroll
    for (int mt = 0; mt < 2; ++mt)
#pragma unroll
        for (int nt = 0; nt < 4; ++nt)
#pragma unroll
            for (int i = 0; i < 4; ++i) acc[mt][nt][i] = 0.f;

    uint4 pp[2], pv;
    {
#pragma unroll
        for (int it = 0; it < 2; ++it) {
            int ch = tid + it * 256;
            int m = ch >> 2, kc = (ch & 3) << 3;
            pp[it] = *(const uint4*)(P + (size_t)(bm + m) * Ss + kc);
        }
        int vn = tid >> 3, vdc = (tid & 7) << 3;
        pv = *(const uint4*)(V + (size_t)vn * HDd + vdc);
    }
#pragma unroll
    for (int it = 0; it < 2; ++it) {
        int ch = tid + it * 256;
        int m = ch >> 2, kc = (ch & 3) << 3;
        *(uint4*)&Ps_[m][kc] = pp[it];
    }
    {
        int vn = tid >> 3, vdc = (tid & 7) << 3;
        H8 t; t.u = pv;
#pragma unroll
        for (int j = 0; j < 8; ++j) Vs_[vdc + j][vn] = t.h[j];
    }
    __syncthreads();

    for (int k0 = 32; k0 <= Ss; k0 += 32) {
        if (k0 < Ss) {
#pragma unroll
            for (int it = 0; it < 2; ++it) {
                int ch = tid + it * 256;
                int m = ch >> 2, kc = (ch & 3) << 3;
                pp[it] = *(const uint4*)(P + (size_t)(bm + m) * Ss + k0 + kc);
            }
            int vn = tid >> 3, vdc = (tid & 7) << 3;
            pv = *(const uint4*)(V + (size_t)(k0 + vn) * HDd + vdc);
        }
#pragma unroll
        for (int ks = 0; ks < 32; ks += 16) {
            uint32_t af[2][4], bf[4][2];
#pragma unroll
            for (int mt = 0; mt < 2; ++mt) {
                int r = warpM + mt * 16 + g;
                af[mt][0] = *(uint32_t*)&Ps_[r][ks + 2*tg];
                af[mt][1] = *(uint32_t*)&Ps_[r + 8][ks + 2*tg];
                af[mt][2] = *(uint32_t*)&Ps_[r][ks + 2*tg + 8];
                af[mt][3] = *(uint32_t*)&Ps_[r + 8][ks + 2*tg + 8];
            }
#pragma unroll
            for (int nt = 0; nt < 4; ++nt) {
                int c = warpN + nt * 8 + g;
                bf[nt][0] = *(uint32_t*)&Vs_[c][ks + 2*tg];
                bf[nt][1] = *(uint32_t*)&Vs_[c][ks + 2*tg + 8];
            }
#pragma unroll
            for (int mt = 0; mt < 2; ++mt)
#pragma unroll
                for (int nt = 0; nt < 4; ++nt)
                    mma_f16(acc[mt][nt], af[mt], bf[nt]);
        }
        if (k0 < Ss) {
            __syncthreads();
#pragma unroll
            for (int it = 0; it < 2; ++it) {
                int ch = tid + it * 256;
                int m = ch >> 2, kc = (ch & 3) << 3;
                *(uint4*)&Ps_[m][kc] = pp[it];
            }
            int vn = tid >> 3, vdc = (tid & 7) << 3;
            H8 t; t.u = pv;
#pragma unroll
            for (int j = 0; j < 8; ++j) Vs_[vdc + j][vn] = t.h[j];
            __syncthreads();
        }
    }
#pragma unroll
    for (int mt = 0; mt < 2; ++mt)
#pragma unroll
        for (int nt = 0; nt < 4; ++nt) {
            int r0 = bm + warpM + mt * 16 + g;
            int c0 = warpN + nt * 8 + 2 * tg;
            *(__half2*)(O + (size_t)r0 * 1024 + c0) =
                __floats2half2_rn(acc[mt][nt][0], acc[mt][nt][1]);
            *(__half2*)(O + (size_t)(r0 + 8) * 1024 + c0) =
                __floats2half2_rn(acc[mt][nt][2], acc[mt][nt][3]);
        }
}

// ---------------------------------------------------------------------------
extern "C" void kernel_launch(void* const* d_in, const int* in_sizes, int n_in,
                              void* d_out, int out_size)
{
    const float* query = (const float*)d_in[0];
    const float* key   = (const float*)d_in[1];
    const float* value = (const float*)d_in[2];
    const float* Wq = (const float*)d_in[3];  const float* bq = (const float*)d_in[4];
    const float* Wk = (const float*)d_in[5];  const float* bk = (const float*)d_in[6];
    const float* Wv = (const float*)d_in[7];  const float* bv = (const float*)d_in[8];
    const float* Wo = (const float*)d_in[9];  const float* bo = (const float*)d_in[10];

    float* out   = (float*)d_out;
    float* probs = out + BSD;

    void* p;
    cudaGetSymbolAddress(&p, g_Wq); __half* gWq = (__half*)p;
    cudaGetSymbolAddress(&p, g_Wk); __half* gWk = (__half*)p;
    cudaGetSymbolAddress(&p, g_Wv); __half* gWv = (__half*)p;
    cudaGetSymbolAddress(&p, g_Wo); __half* gWo = (__half*)p;
    cudaGetSymbolAddress(&p, g_bp); float*  gbp = (float*)p;
    cudaGetSymbolAddress(&p, g_Qh); __half* gQh = (__half*)p;
    cudaGetSymbolAddress(&p, g_Kh); __half* gKh = (__half*)p;
    cudaGetSymbolAddress(&p, g_Vh); __half* gVh = (__half*)p;
    cudaGetSymbolAddress(&p, g_A);  __half* gA  = (__half*)p;

    static int smem_set = 0;
    if (!smem_set) {
        cudaFuncSetAttribute(fused_scores_softmax,
                             cudaFuncAttributeMaxDynamicSharedMemorySize, FUSED_SMEM);
        smem_set = 1;
    }

    dim3 gemm_grid(Dd/128, MM/128);   // (8, 32)

    // 0) Weight/bias permutations (fp16, transposed)
    perm_wT<<<64, 256>>>(Wq, gWq);
    perm_wT<<<64, 256>>>(Wk, gWk);
    perm_wT<<<64, 256>>>(Wv, gWv);
    perm_woT<<<64, 256>>>(Wo, gWo);
    perm_bias<<<12, 256>>>(bq, bk, bv, gbp);

    // 1) Projections -> fp16 head layout
    gemm_f16_headout<<<gemm_grid, 256>>>(query, gWq, gbp,        gQh);
    gemm_f16_headout<<<gemm_grid, 256>>>(key,   gWk, gbp + 1024, gKh);
    gemm_f16_headout<<<gemm_grid, 256>>>(value, gWv, gbp + 2048, gVh);

    // 2+3) Fused scores + head-softmax: probs (d_out) + fp16 P planes
    fused_scores_softmax<<<dim3(Ss/64, Ss/32, Bb), 256, FUSED_SMEM>>>(probs);

    // 4) Attn*V (fp16) -> interleaved fp16 activations
    attnv_f16<<<dim3(Ss/128, Bb*NHh), 256>>>();

    // 5) Output projection (fp16 inputs, fp32 out)
    gemm_f16_bias<<<gemm_grid, 256>>>(gA, gWo, bo, out);
}

// round 16
// speedup vs baseline: 1.3160x; 1.3160x over previous
#include <cuda_runtime.h>
#include <cuda_fp16.h>
#include <math.h>
#include <stdint.h>

// Problem constants
#define Bb   2
#define Ss   2048
#define Dd   1024
#define NHh  16
#define HDd  64
#define MM   (Bb*Ss)
#define PLANE (Ss*Ss)
#define BSD  (Bb*Ss*Dd)

// ---------------- scratch (device globals) ----------------
__device__ __half g_Wq[Dd*Dd];     // permuted+transposed: [n'][k] fp16
__device__ __half g_Wk[Dd*Dd];
__device__ __half g_Wv[Dd*Dd];
__device__ __half g_Wo[Dd*Dd];     // row-permuted+transposed
__device__ float  g_bp[3*Dd];      // permuted biases (q,k,v)
__device__ __half g_Qh[BSD];       // [b,h,s,d] fp16
__device__ __half g_Kh[BSD];
__device__ __half g_Vh[BSD];
__device__ __half g_A[BSD];        // merged activations [b,s,h*64+d] fp16
__device__ __half g_Sc[134217728]; // raw scaled scores [b,h,l,n] fp16
__device__ __half g_P[134217728];  // normalized probs  [b,h,l,n] fp16

// ---------------------------------------------------------------------------
// helpers
// ---------------------------------------------------------------------------
__device__ __forceinline__ void mma_f16(float* c, const uint32_t* a, const uint32_t* b) {
    asm volatile(
        "mma.sync.aligned.m16n8k16.row.col.f32.f16.f16.f32 "
        "{%0,%1,%2,%3}, {%4,%5,%6,%7}, {%8,%9}, {%0,%1,%2,%3};\n"
        : "+f"(c[0]), "+f"(c[1]), "+f"(c[2]), "+f"(c[3])
        : "r"(a[0]), "r"(a[1]), "r"(a[2]), "r"(a[3]), "r"(b[0]), "r"(b[1]));
}

union H8 { __half h[8]; uint4 u; };
union H16 { __half h[16]; uint4 u[2]; };

// ---------------------------------------------------------------------------
// perm_wT: Wt[h*64+d][r] = (half) W[r][d*16+h]   (for Wq/Wk/Wv)
// ---------------------------------------------------------------------------
__global__ __launch_bounds__(256) void perm_wT(
    const float* __restrict__ W, __half* __restrict__ Wt)
{
    __shared__ __half sm[16][1040];
    const int r0 = blockIdx.x * 16;
    const int tid = threadIdx.x;
#pragma unroll
    for (int it = 0; it < 16; ++it) {
        int ch = it * 256 + tid;
        int r = ch >> 8, c4 = (ch & 255) << 2;
        float4 v = *(const float4*)(W + (size_t)(r0 + r) * Dd + c4);
        *(__half2*)&sm[r][c4]     = __floats2half2_rn(v.x, v.y);
        *(__half2*)&sm[r][c4 + 2] = __floats2half2_rn(v.z, v.w);
    }
    __syncthreads();
#pragma unroll
    for (int i = 0; i < 4; ++i) {
        int cp = tid + i * 256;
        int src = ((cp & 63) << 4) + (cp >> 6);
        H16 t;
#pragma unroll
        for (int r = 0; r < 16; ++r) t.h[r] = sm[r][src];
        uint4* dst = (uint4*)(Wt + (size_t)cp * Dd + r0);
        dst[0] = t.u[0];
        dst[1] = t.u[1];
    }
}

// ---------------------------------------------------------------------------
// perm_woT: Wt[c][j] = (half) Wo[(j&63)*16 + (j>>6)][c]
// ---------------------------------------------------------------------------
__global__ __launch_bounds__(256) void perm_woT(
    const float* __restrict__ Wo, __half* __restrict__ Wt)
{
    __shared__ __half sm[1024][20];
    const int c0 = blockIdx.x * 16;
    const int tid = threadIdx.x;
#pragma unroll
    for (int it = 0; it < 16; ++it) {
        int ch = it * 256 + tid;
        int r = ch >> 2, c4 = (ch & 3) << 2;
        float4 v = *(const float4*)(Wo + (size_t)r * Dd + c0 + c4);
        *(__half2*)&sm[r][c4]     = __floats2half2_rn(v.x, v.y);
        *(__half2*)&sm[r][c4 + 2] = __floats2half2_rn(v.z, v.w);
    }
    __syncthreads();
    const int lc = tid >> 4;
    const int jc = tid & 15;
#pragma unroll
    for (int it = 0; it < 8; ++it) {
        int j0 = jc * 8 + it * 128;
        H8 t;
#pragma unroll
        for (int i = 0; i < 8; ++i) {
            int j = j0 + i;
            int src = ((j & 63) << 4) + (j >> 6);
            t.h[i] = sm[src][lc];
        }
        *(uint4*)(Wt + (size_t)(c0 + lc) * Dd + j0) = t.u;
    }
}

// perm_bias: bp[w*1024 + h*64+d] = b_w[d*16+h]
__global__ __launch_bounds__(256) void perm_bias(
    const float* __restrict__ b0, const float* __restrict__ b1,
    const float* __restrict__ b2, float* __restrict__ bp)
{
    int i = threadIdx.x + blockIdx.x * 256;
    int w = i >> 10, j = i & 1023;
    const float* src = (w == 0) ? b0 : ((w == 1) ? b1 : b2);
    bp[i] = src[((j & 63) << 4) + (j >> 6)];
}

// ---------------------------------------------------------------------------
// Projection GEMM (f16 mma, fp32 in): Oh[b,h,s,d] = (x @ W')[m, h*64+d] + bp
// ---------------------------------------------------------------------------
__global__ __launch_bounds__(256) void gemm_f16_headout(
    const float* __restrict__ A, const __half* __restrict__ Wt,
    const float* __restrict__ bp, __half* __restrict__ Oh)
{
    __shared__ __half As_[128][40];
    __shared__ __half Bs_[128][40];
    const int tid  = threadIdx.x;
    const int lane = tid & 31, w = tid >> 5;
    const int g = lane >> 2, tg = lane & 3;
    const int bm = blockIdx.y * 128, bn = blockIdx.x * 128;
    const int warpM = (w >> 2) * 64, warpN = (w & 3) * 32;

    float acc[4][4][4];
#pragma unroll
    for (int mt = 0; mt < 4; ++mt)
#pragma unroll
        for (int nt = 0; nt < 4; ++nt)
#pragma unroll
            for (int i = 0; i < 4; ++i) acc[mt][nt][i] = 0.f;

    float4 pa[4]; uint4 pw[2];
#pragma unroll
    for (int it = 0; it < 4; ++it) {
        int ch = tid + it * 256;
        int m = ch >> 3, kq = (ch & 7) << 2;
        pa[it] = *(const float4*)(A + (size_t)(bm + m) * Dd + kq);
    }
#pragma unroll
    for (int it = 0; it < 2; ++it) {
        int ch = tid + it * 256;
        int n = ch >> 2, kc = (ch & 3) << 3;
        pw[it] = *(const uint4*)(Wt + (size_t)(bn + n) * Dd + kc);
    }
#pragma unroll
    for (int it = 0; it < 4; ++it) {
        int ch = tid + it * 256;
        int m = ch >> 3, kq = (ch & 7) << 2;
        *(__half2*)&As_[m][kq]     = __floats2half2_rn(pa[it].x, pa[it].y);
        *(__half2*)&As_[m][kq + 2] = __floats2half2_rn(pa[it].z, pa[it].w);
    }
#pragma unroll
    for (int it = 0; it < 2; ++it) {
        int ch = tid + it * 256;
        int n = ch >> 2, kc = (ch & 3) << 3;
        *(uint4*)&Bs_[n][kc] = pw[it];
    }
    __syncthreads();

    for (int k0 = 32; k0 <= Dd; k0 += 32) {
        if (k0 < Dd) {
#pragma unroll
            for (int it = 0; it < 4; ++it) {
                int ch = tid + it * 256;
                int m = ch >> 3, kq = (ch & 7) << 2;
                pa[it] = *(const float4*)(A + (size_t)(bm + m) * Dd + k0 + kq);
            }
#pragma unroll
            for (int it = 0; it < 2; ++it) {
                int ch = tid + it * 256;
                int n = ch >> 2, kc = (ch & 3) << 3;
                pw[it] = *(const uint4*)(Wt + (size_t)(bn + n) * Dd + k0 + kc);
            }
        }
#pragma unroll
        for (int ks = 0; ks < 32; ks += 16) {
            uint32_t af[4][4], bf[4][2];
#pragma unroll
            for (int mt = 0; mt < 4; ++mt) {
                int r = warpM + mt * 16 + g;
                af[mt][0] = *(uint32_t*)&As_[r][ks + 2*tg];
                af[mt][1] = *(uint32_t*)&As_[r + 8][ks + 2*tg];
                af[mt][2] = *(uint32_t*)&As_[r][ks + 2*tg + 8];
                af[mt][3] = *(uint32_t*)&As_[r + 8][ks + 2*tg + 8];
            }
#pragma unroll
            for (int nt = 0; nt < 4; ++nt) {
                int c = warpN + nt * 8 + g;
                bf[nt][0] = *(uint32_t*)&Bs_[c][ks + 2*tg];
                bf[nt][1] = *(uint32_t*)&Bs_[c][ks + 2*tg + 8];
            }
#pragma unroll
            for (int mt = 0; mt < 4; ++mt)
#pragma unroll
                for (int nt = 0; nt < 4; ++nt)
                    mma_f16(acc[mt][nt], af[mt], bf[nt]);
        }
        if (k0 < Dd) {
            __syncthreads();
#pragma unroll
            for (int it = 0; it < 4; ++it) {
                int ch = tid + it * 256;
                int m = ch >> 3, kq = (ch & 7) << 2;
                *(__half2*)&As_[m][kq]     = __floats2half2_rn(pa[it].x, pa[it].y);
                *(__half2*)&As_[m][kq + 2] = __floats2half2_rn(pa[it].z, pa[it].w);
            }
#pragma unroll
            for (int it = 0; it < 2; ++it) {
                int ch = tid + it * 256;
                int n = ch >> 2, kc = (ch & 3) << 3;
                *(uint4*)&Bs_[n][kc] = pw[it];
            }
            __syncthreads();
        }
    }

#pragma unroll
    for (int mt = 0; mt < 4; ++mt)
#pragma unroll
        for (int nt = 0; nt < 4; ++nt) {
            int r0 = bm + warpM + mt * 16 + g;
            int c0 = bn + warpN + nt * 8 + 2 * tg;
            int b = r0 >> 11, s = r0 & 2047;
            int h = c0 >> 6, d = c0 & 63;
            float b0 = bp[c0], b1 = bp[c0 + 1];
            __half* dst = Oh + ((size_t)(b * 16 + h) * 2048 + s) * 64 + d;
            *(__half2*)(dst)          = __floats2half2_rn(acc[mt][nt][0] + b0, acc[mt][nt][1] + b1);
            *(__half2*)(dst + 8 * 64) = __floats2half2_rn(acc[mt][nt][2] + b0, acc[mt][nt][3] + b1);
        }
}

// ---------------------------------------------------------------------------
// Output projection (f16 x f16 -> fp32): out = g_A @ Wo' + bo
// ---------------------------------------------------------------------------
__global__ __launch_bounds__(256) void gemm_f16_bias(
    const __half* __restrict__ A, const __half* __restrict__ Wt,
    const float* __restrict__ bias, float* __restrict__ C)
{
    __shared__ __half As_[128][40];
    __shared__ __half Bs_[128][40];
    const int tid  = threadIdx.x;
    const int lane = tid & 31, w = tid >> 5;
    const int g = lane >> 2, tg = lane & 3;
    const int bm = blockIdx.y * 128, bn = blockIdx.x * 128;
    const int warpM = (w >> 2) * 64, warpN = (w & 3) * 32;

    float acc[4][4][4];
#pragma unroll
    for (int mt = 0; mt < 4; ++mt)
#pragma unroll
        for (int nt = 0; nt < 4; ++nt)
#pragma unroll
            for (int i = 0; i < 4; ++i) acc[mt][nt][i] = 0.f;

    uint4 pa[2], pw[2];
#pragma unroll
    for (int it = 0; it < 2; ++it) {
        int ch = tid + it * 256;
        int m = ch >> 2, kc = (ch & 3) << 3;
        pa[it] = *(const uint4*)(A + (size_t)(bm + m) * Dd + kc);
        pw[it] = *(const uint4*)(Wt + (size_t)(bn + m) * Dd + kc);
    }
#pragma unroll
    for (int it = 0; it < 2; ++it) {
        int ch = tid + it * 256;
        int m = ch >> 2, kc = (ch & 3) << 3;
        *(uint4*)&As_[m][kc] = pa[it];
        *(uint4*)&Bs_[m][kc] = pw[it];
    }
    __syncthreads();

    for (int k0 = 32; k0 <= Dd; k0 += 32) {
        if (k0 < Dd) {
#pragma unroll
            for (int it = 0; it < 2; ++it) {
                int ch = tid + it * 256;
                int m = ch >> 2, kc = (ch & 3) << 3;
                pa[it] = *(const uint4*)(A + (size_t)(bm + m) * Dd + k0 + kc);
                pw[it] = *(const uint4*)(Wt + (size_t)(bn + m) * Dd + k0 + kc);
            }
        }
#pragma unroll
        for (int ks = 0; ks < 32; ks += 16) {
            uint32_t af[4][4], bf[4][2];
#pragma unroll
            for (int mt = 0; mt < 4; ++mt) {
                int r = warpM + mt * 16 + g;
                af[mt][0] = *(uint32_t*)&As_[r][ks + 2*tg];
                af[mt][1] = *(uint32_t*)&As_[r + 8][ks + 2*tg];
                af[mt][2] = *(uint32_t*)&As_[r][ks + 2*tg + 8];
                af[mt][3] = *(uint32_t*)&As_[r + 8][ks + 2*tg + 8];
            }
#pragma unroll
            for (int nt = 0; nt < 4; ++nt) {
                int c = warpN + nt * 8 + g;
                bf[nt][0] = *(uint32_t*)&Bs_[c][ks + 2*tg];
                bf[nt][1] = *(uint32_t*)&Bs_[c][ks + 2*tg + 8];
            }
#pragma unroll
            for (int mt = 0; mt < 4; ++mt)
#pragma unroll
                for (int nt = 0; nt < 4; ++nt)
                    mma_f16(acc[mt][nt], af[mt], bf[nt]);
        }
        if (k0 < Dd) {
            __syncthreads();
#pragma unroll
            for (int it = 0; it < 2; ++it) {
                int ch = tid + it * 256;
                int m = ch >> 2, kc = (ch & 3) << 3;
                *(uint4*)&As_[m][kc] = pa[it];
                *(uint4*)&Bs_[m][kc] = pw[it];
            }
            __syncthreads();
        }
    }
#pragma unroll
    for (int mt = 0; mt < 4; ++mt)
#pragma unroll
        for (int nt = 0; nt < 4; ++nt) {
            int r0 = bm + warpM + mt * 16 + g;
            int c0 = bn + warpN + nt * 8 + 2 * tg;
            float b0 = bias[c0], b1 = bias[c0 + 1];
            float2 v0 = {acc[mt][nt][0] + b0, acc[mt][nt][1] + b1};
            float2 v1 = {acc[mt][nt][2] + b0, acc[mt][nt][3] + b1};
            *(float2*)(C + (size_t)r0 * Dd + c0) = v0;
            *(float2*)(C + (size_t)(r0 + 8) * Dd + c0) = v1;
        }
}

// ---------------------------------------------------------------------------
// Scores (f16): per plane z: Sc[l,n] = 0.125 * Qh[l,:].Kh[n,:], K=64 one-shot.
// Output now fp16 (halves the dominant store stream).
// ---------------------------------------------------------------------------
__global__ __launch_bounds__(256) void scores_f16()
{
    __shared__ __half Qs_[128][72];
    __shared__ __half Ks_[128][72];
    const int tid  = threadIdx.x;
    const int lane = tid & 31, w = tid >> 5;
    const int g = lane >> 2, tg = lane & 3;
    const int z  = blockIdx.z;
    const int bm = blockIdx.y * 128, bn = blockIdx.x * 128;
    const int warpM = (w >> 2) * 64, warpN = (w & 3) * 32;
    const __half* Q  = g_Qh + (size_t)z * (Ss*HDd);
    const __half* Kp = g_Kh + (size_t)z * (Ss*HDd);

    float acc[4][4][4];
#pragma unroll
    for (int mt = 0; mt < 4; ++mt)
#pragma unroll
        for (int nt = 0; nt < 4; ++nt)
#pragma unroll
            for (int i = 0; i < 4; ++i) acc[mt][nt][i] = 0.f;

#pragma unroll
    for (int it = 0; it < 4; ++it) {
        int ch = tid + it * 256;
        int s = ch >> 3, dc = (ch & 7) << 3;
        *(uint4*)&Qs_[s][dc] = *(const uint4*)(Q  + (size_t)(bm + s) * HDd + dc);
        *(uint4*)&Ks_[s][dc] = *(const uint4*)(Kp + (size_t)(bn + s) * HDd + dc);
    }
    __syncthreads();

#pragma unroll
    for (int ks = 0; ks < 64; ks += 16) {
        uint32_t af[4][4], bf[4][2];
#pragma unroll
        for (int mt = 0; mt < 4; ++mt) {
            int r = warpM + mt * 16 + g;
            af[mt][0] = *(uint32_t*)&Qs_[r][ks + 2*tg];
            af[mt][1] = *(uint32_t*)&Qs_[r + 8][ks + 2*tg];
            af[mt][2] = *(uint32_t*)&Qs_[r][ks + 2*tg + 8];
            af[mt][3] = *(uint32_t*)&Qs_[r + 8][ks + 2*tg + 8];
        }
#pragma unroll
        for (int nt = 0; nt < 4; ++nt) {
            int c = warpN + nt * 8 + g;
            bf[nt][0] = *(uint32_t*)&Ks_[c][ks + 2*tg];
            bf[nt][1] = *(uint32_t*)&Ks_[c][ks + 2*tg + 8];
        }
#pragma unroll
        for (int mt = 0; mt < 4; ++mt)
#pragma unroll
            for (int nt = 0; nt < 4; ++nt)
                mma_f16(acc[mt][nt], af[mt], bf[nt]);
    }

    __half* out = g_Sc + (size_t)z * PLANE;
#pragma unroll
    for (int mt = 0; mt < 4; ++mt)
#pragma unroll
        for (int nt = 0; nt < 4; ++nt) {
            int r0 = bm + warpM + mt * 16 + g;
            int c0 = bn + warpN + nt * 8 + 2 * tg;
            *(__half2*)(out + (size_t)r0 * Ss + c0) =
                __floats2half2_rn(0.125f*acc[mt][nt][0], 0.125f*acc[mt][nt][1]);
            *(__half2*)(out + (size_t)(r0 + 8) * Ss + c0) =
                __floats2half2_rn(0.125f*acc[mt][nt][2], 0.125f*acc[mt][nt][3]);
        }
}

// ---------------------------------------------------------------------------
// Softmax over HEAD axis. Reads raw fp16 scores; writes fp32 probs (output)
// and fp16 normalized P planes (g_P) for attn*V.
// ---------------------------------------------------------------------------
__global__ __launch_bounds__(256) void softmax_kernel(float* __restrict__ probs)
{
    int i = blockIdx.x * 256 + threadIdx.x;
    int n = i & 2047;
    int l = (i >> 11) & 2047;
    int b = i >> 22;
    size_t off = (size_t)l * Ss + n;

    float s[16];
#pragma unroll
    for (int h = 0; h < 16; ++h)
        s[h] = __half2float(g_Sc[(size_t)(b*16 + h) * PLANE + off]);

    float m = s[0];
#pragma unroll
    for (int h = 1; h < 16; ++h) m = fmaxf(m, s[h]);
    float sum = 0.f;
#pragma unroll
    for (int h = 0; h < 16; ++h) { s[h] = __expf(s[h] - m); sum += s[h]; }
    float r = 1.0f / sum;

    float* po = probs + (size_t)i * 16;
#pragma unroll
    for (int h4 = 0; h4 < 16; h4 += 4) {
        float4 o = {s[h4]*r, s[h4+1]*r, s[h4+2]*r, s[h4+3]*r};
        *(float4*)(po + h4) = o;
    }
#pragma unroll
    for (int h = 0; h < 16; ++h)
        g_P[(size_t)(b*16 + h) * PLANE + off] = __float2half_rn(s[h] * r);
}

// ---------------------------------------------------------------------------
// Attn*V (f16): per plane z: O[l,d] = sum_n P[l,n] * V[n,d]
// M=128-tile, N=64, K=2048, BK=64 (halved sync count vs BK=32).
// V transposed to [d][n] at smem store. Writes g_A interleaved fp16.
// ---------------------------------------------------------------------------
__global__ __launch_bounds__(256) void attnv_f16()
{
    __shared__ __half Ps_[128][72];   // [l][k-chunk 64]
    __shared__ __half Vs_[64][72];    // [d][k-chunk 64]
    const int tid  = threadIdx.x;
    const int lane = tid & 31, w = tid >> 5;
    const int g = lane >> 2, tg = lane & 3;
    const int z  = blockIdx.y;
    const int bm = blockIdx.x * 128;
    const int warpM = (w >> 1) * 32, warpN = (w & 1) * 32;
    const __half* P = g_P + (size_t)z * PLANE;
    const __half* V = g_Vh + (size_t)z * (Ss*HDd);
    const int bz = z >> 4, hz = z & 15;
    __half* O = g_A + ((size_t)bz * 2048) * 1024 + hz * 64;

    float acc[2][4][4];
#pragma unroll
    for (int mt = 0; mt < 2; ++mt)
#pragma unroll
        for (int nt = 0; nt < 4; ++nt)
#pragma unroll
            for (int i = 0; i < 4; ++i) acc[mt][nt][i] = 0.f;

    // P tile: 128 rows x 64 k halves = 1024 uint4 -> 4/thread
    // V tile: 64 seq x 64 d halves = 512 uint4 -> 2/thread (transposed store)
    uint4 pp[4], pv[2];
    {
#pragma unroll
        for (int it = 0; it < 4; ++it) {
            int ch = tid + it * 256;
            int m = ch >> 3, kc = (ch & 7) << 3;
            pp[it] = *(const uint4*)(P + (size_t)(bm + m) * Ss + kc);
        }
#pragma unroll
        for (int it = 0; it < 2; ++it) {
            int ch = tid + it * 256;
            int vn = ch >> 3, vdc = (ch & 7) << 3;
            pv[it] = *(const uint4*)(V + (size_t)vn * HDd + vdc);
        }
    }
#pragma unroll
    for (int it = 0; it < 4; ++it) {
        int ch = tid + it * 256;
        int m = ch >> 3, kc = (ch & 7) << 3;
        *(uint4*)&Ps_[m][kc] = pp[it];
    }
#pragma unroll
    for (int it = 0; it < 2; ++it) {
        int ch = tid + it * 256;
        int vn = ch >> 3, vdc = (ch & 7) << 3;
        H8 t; t.u = pv[it];
#pragma unroll
        for (int j = 0; j < 8; ++j) Vs_[vdc + j][vn] = t.h[j];
    }
    __syncthreads();

    for (int k0 = 64; k0 <= Ss; k0 += 64) {
        if (k0 < Ss) {
#pragma unroll
            for (int it = 0; it < 4; ++it) {
                int ch = tid + it * 256;
                int m = ch >> 3, kc = (ch & 7) << 3;
                pp[it] = *(const uint4*)(P + (size_t)(bm + m) * Ss + k0 + kc);
            }
#pragma unroll
            for (int it = 0; it < 2; ++it) {
                int ch = tid + it * 256;
                int vn = ch >> 3, vdc = (ch & 7) << 3;
                pv[it] = *(const uint4*)(V + (size_t)(k0 + vn) * HDd + vdc);
            }
        }
#pragma unroll
        for (int ks = 0; ks < 64; ks += 16) {
            uint32_t af[2][4], bf[4][2];
#pragma unroll
            for (int mt = 0; mt < 2; ++mt) {
                int r = warpM + mt * 16 + g;
                af[mt][0] = *(uint32_t*)&Ps_[r][ks + 2*tg];
                af[mt][1] = *(uint32_t*)&Ps_[r + 8][ks + 2*tg];
                af[mt][2] = *(uint32_t*)&Ps_[r][ks + 2*tg + 8];
                af[mt][3] = *(uint32_t*)&Ps_[r + 8][ks + 2*tg + 8];
            }
#pragma unroll
            for (int nt = 0; nt < 4; ++nt) {
                int c = warpN + nt * 8 + g;
                bf[nt][0] = *(uint32_t*)&Vs_[c][ks + 2*tg];
                bf[nt][1] = *(uint32_t*)&Vs_[c][ks + 2*tg + 8];
            }
#pragma unroll
            for (int mt = 0; mt < 2; ++mt)
#pragma unroll
                for (int nt = 0; nt < 4; ++nt)
                    mma_f16(acc[mt][nt], af[mt], bf[nt]);
        }
        if (k0 < Ss) {
            __syncthreads();
#pragma unroll
            for (int it = 0; it < 4; ++it) {
                int ch = tid + it * 256;
                int m = ch >> 3, kc = (ch & 7) << 3;
                *(uint4*)&Ps_[m][kc] = pp[it];
            }
#pragma unroll
            for (int it = 0; it < 2; ++it) {
                int ch = tid + it * 256;
                int vn = ch >> 3, vdc = (ch & 7) << 3;
                H8 t; t.u = pv[it];
#pragma unroll
                for (int j = 0; j < 8; ++j) Vs_[vdc + j][vn] = t.h[j];
            }
            __syncthreads();
        }
    }
#pragma unroll
    for (int mt = 0; mt < 2; ++mt)
#pragma unroll
        for (int nt = 0; nt < 4; ++nt) {
            int r0 = bm + warpM + mt * 16 + g;
            int c0 = warpN + nt * 8 + 2 * tg;
            *(__half2*)(O + (size_t)r0 * 1024 + c0) =
                __floats2half2_rn(acc[mt][nt][0], acc[mt][nt][1]);
            *(__half2*)(O + (size_t)(r0 + 8) * 1024 + c0) =
                __floats2half2_rn(acc[mt][nt][2], acc[mt][nt][3]);
        }
}

// ---------------------------------------------------------------------------
extern "C" void kernel_launch(void* const* d_in, const int* in_sizes, int n_in,
                              void* d_out, int out_size)
{
    const float* query = (const float*)d_in[0];
    const float* key   = (const float*)d_in[1];
    const float* value = (const float*)d_in[2];
    const float* Wq = (const float*)d_in[3];  const float* bq = (const float*)d_in[4];
    const float* Wk = (const float*)d_in[5];  const float* bk = (const float*)d_in[6];
    const float* Wv = (const float*)d_in[7];  const float* bv = (const float*)d_in[8];
    const float* Wo = (const float*)d_in[9];  const float* bo = (const float*)d_in[10];

    float* out   = (float*)d_out;
    float* probs = out + BSD;

    void* p;
    cudaGetSymbolAddress(&p, g_Wq); __half* gWq = (__half*)p;
    cudaGetSymbolAddress(&p, g_Wk); __half* gWk = (__half*)p;
    cudaGetSymbolAddress(&p, g_Wv); __half* gWv = (__half*)p;
    cudaGetSymbolAddress(&p, g_Wo); __half* gWo = (__half*)p;
    cudaGetSymbolAddress(&p, g_bp); float*  gbp = (float*)p;
    cudaGetSymbolAddress(&p, g_Qh); __half* gQh = (__half*)p;
    cudaGetSymbolAddress(&p, g_Kh); __half* gKh = (__half*)p;
    cudaGetSymbolAddress(&p, g_Vh); __half* gVh = (__half*)p;
    cudaGetSymbolAddress(&p, g_A);  __half* gA  = (__half*)p;

    dim3 gemm_grid(Dd/128, MM/128);   // (8, 32)

    // 0) Weight/bias permutations (fp16, transposed)
    perm_wT<<<64, 256>>>(Wq, gWq);
    perm_wT<<<64, 256>>>(Wk, gWk);
    perm_wT<<<64, 256>>>(Wv, gWv);
    perm_woT<<<64, 256>>>(Wo, gWo);
    perm_bias<<<12, 256>>>(bq, bk, bv, gbp);

    // 1) Projections -> fp16 head layout
    gemm_f16_headout<<<gemm_grid, 256>>>(query, gWq, gbp,        gQh);
    gemm_f16_headout<<<gemm_grid, 256>>>(key,   gWk, gbp + 1024, gKh);
    gemm_f16_headout<<<gemm_grid, 256>>>(value, gWv, gbp + 2048, gVh);

    // 2) Per-head raw scores (fp16) into g_Sc
    scores_f16<<<dim3(Ss/128, Ss/128, Bb*NHh), 256>>>();

    // 3) Softmax over heads: fp32 probs output + fp16 P planes
    softmax_kernel<<<(Bb*(size_t)Ss*Ss)/256, 256>>>(probs);

    // 4) Attn*V (fp16, BK=64) -> interleaved fp16 activations
    attnv_f16<<<dim3(Ss/128, Bb*NHh), 256>>>();

    // 5) Output projection (fp16 inputs, fp32 out)
    gemm_f16_bias<<<gemm_grid, 256>>>(gA, gWo, bo, out);
}

// round 17
// speedup vs baseline: 1.3387x; 1.0172x over previous
#include <cuda_runtime.h>
#include <cuda_fp16.h>
#include <math.h>
#include <stdint.h>

// Problem constants
#define Bb   2
#define Ss   2048
#define Dd   1024
#define NHh  16
#define HDd  64
#define MM   (Bb*Ss)
#define PLANE (Ss*Ss)
#define BSD  (Bb*Ss*Dd)

// ---------------- scratch (device globals) ----------------
__device__ __half g_Wq[Dd*Dd];     // permuted+transposed: [n'][k] fp16
__device__ __half g_Wk[Dd*Dd];
__device__ __half g_Wv[Dd*Dd];
__device__ __half g_Wo[Dd*Dd];     // row-permuted+transposed
__device__ float  g_bp[3*Dd];      // permuted biases (q,k,v)
__device__ __half g_X[3*BSD];      // fp16 copies of query/key/value [3][4096][1024]
__device__ __half g_Qh[BSD];       // [b,h,s,d] fp16
__device__ __half g_Kh[BSD];
__device__ __half g_Vh[BSD];
__device__ __half g_A[BSD];        // merged activations [b,s,h*64+d] fp16
__device__ __half g_Sc[134217728]; // raw scaled scores [b,h,l,n] fp16
__device__ __half g_P[134217728];  // normalized probs  [b,h,l,n] fp16

// ---------------------------------------------------------------------------
// helpers
// ---------------------------------------------------------------------------
__device__ __forceinline__ void mma_f16(float* c, const uint32_t* a, const uint32_t* b) {
    asm volatile(
        "mma.sync.aligned.m16n8k16.row.col.f32.f16.f16.f32 "
        "{%0,%1,%2,%3}, {%4,%5,%6,%7}, {%8,%9}, {%0,%1,%2,%3};\n"
        : "+f"(c[0]), "+f"(c[1]), "+f"(c[2]), "+f"(c[3])
        : "r"(a[0]), "r"(a[1]), "r"(a[2]), "r"(a[3]), "r"(b[0]), "r"(b[1]));
}

union H8 { __half h[8]; uint4 u; };
union H16 { __half h[16]; uint4 u[2]; };

// ---------------------------------------------------------------------------
// conv_f16: fp32 -> fp16 bulk convert (8 elems/thread)
// ---------------------------------------------------------------------------
__global__ __launch_bounds__(256) void conv_f16(
    const float* __restrict__ in, __half* __restrict__ out)
{
    int i = (blockIdx.x * 256 + threadIdx.x) * 8;
    float4 a = *(const float4*)(in + i);
    float4 b = *(const float4*)(in + i + 4);
    H8 t;
    *(__half2*)&t.h[0] = __floats2half2_rn(a.x, a.y);
    *(__half2*)&t.h[2] = __floats2half2_rn(a.z, a.w);
    *(__half2*)&t.h[4] = __floats2half2_rn(b.x, b.y);
    *(__half2*)&t.h[6] = __floats2half2_rn(b.z, b.w);
    *(uint4*)(out + i) = t.u;
}

// ---------------------------------------------------------------------------
// perm_wT: Wt[h*64+d][r] = (half) W[r][d*16+h]   (for Wq/Wk/Wv)
// ---------------------------------------------------------------------------
__global__ __launch_bounds__(256) void perm_wT(
    const float* __restrict__ W, __half* __restrict__ Wt)
{
    __shared__ __half sm[16][1040];
    const int r0 = blockIdx.x * 16;
    const int tid = threadIdx.x;
#pragma unroll
    for (int it = 0; it < 16; ++it) {
        int ch = it * 256 + tid;
        int r = ch >> 8, c4 = (ch & 255) << 2;
        float4 v = *(const float4*)(W + (size_t)(r0 + r) * Dd + c4);
        *(__half2*)&sm[r][c4]     = __floats2half2_rn(v.x, v.y);
        *(__half2*)&sm[r][c4 + 2] = __floats2half2_rn(v.z, v.w);
    }
    __syncthreads();
#pragma unroll
    for (int i = 0; i < 4; ++i) {
        int cp = tid + i * 256;
        int src = ((cp & 63) << 4) + (cp >> 6);
        H16 t;
#pragma unroll
        for (int r = 0; r < 16; ++r) t.h[r] = sm[r][src];
        uint4* dst = (uint4*)(Wt + (size_t)cp * Dd + r0);
        dst[0] = t.u[0];
        dst[1] = t.u[1];
    }
}

// ---------------------------------------------------------------------------
// perm_woT: Wt[c][j] = (half) Wo[(j&63)*16 + (j>>6)][c]
// ---------------------------------------------------------------------------
__global__ __launch_bounds__(256) void perm_woT(
    const float* __restrict__ Wo, __half* __restrict__ Wt)
{
    __shared__ __half sm[1024][20];
    const int c0 = blockIdx.x * 16;
    const int tid = threadIdx.x;
#pragma unroll
    for (int it = 0; it < 16; ++it) {
        int ch = it * 256 + tid;
        int r = ch >> 2, c4 = (ch & 3) << 2;
        float4 v = *(const float4*)(Wo + (size_t)r * Dd + c0 + c4);
        *(__half2*)&sm[r][c4]     = __floats2half2_rn(v.x, v.y);
        *(__half2*)&sm[r][c4 + 2] = __floats2half2_rn(v.z, v.w);
    }
    __syncthreads();
    const int lc = tid >> 4;
    const int jc = tid & 15;
#pragma unroll
    for (int it = 0; it < 8; ++it) {
        int j0 = jc * 8 + it * 128;
        H8 t;
#pragma unroll
        for (int i = 0; i < 8; ++i) {
            int j = j0 + i;
            int src = ((j & 63) << 4) + (j >> 6);
            t.h[i] = sm[src][lc];
        }
        *(uint4*)(Wt + (size_t)(c0 + lc) * Dd + j0) = t.u;
    }
}

// perm_bias: bp[w*1024 + h*64+d] = b_w[d*16+h]
__global__ __launch_bounds__(256) void perm_bias(
    const float* __restrict__ b0, const float* __restrict__ b1,
    const float* __restrict__ b2, float* __restrict__ bp)
{
    int i = threadIdx.x + blockIdx.x * 256;
    int w = i >> 10, j = i & 1023;
    const float* src = (w == 0) ? b0 : ((w == 1) ? b1 : b2);
    bp[i] = src[((j & 63) << 4) + (j >> 6)];
}

// ---------------------------------------------------------------------------
// Projection GEMM (all-fp16 in): Oh[b,h,s,d] = (X @ W')[m, h*64+d] + bp
// Block 128x128, BK=32, 8 warps (2m x 4n). Reg-prefetch double buffer.
// ---------------------------------------------------------------------------
__global__ __launch_bounds__(256) void gemm_f16_headout(
    const __half* __restrict__ A, const __half* __restrict__ Wt,
    const float* __restrict__ bp, __half* __restrict__ Oh)
{
    __shared__ __half As_[128][40];
    __shared__ __half Bs_[128][40];
    const int tid  = threadIdx.x;
    const int lane = tid & 31, w = tid >> 5;
    const int g = lane >> 2, tg = lane & 3;
    const int bm = blockIdx.y * 128, bn = blockIdx.x * 128;
    const int warpM = (w >> 2) * 64, warpN = (w & 3) * 32;

    float acc[4][4][4];
#pragma unroll
    for (int mt = 0; mt < 4; ++mt)
#pragma unroll
        for (int nt = 0; nt < 4; ++nt)
#pragma unroll
            for (int i = 0; i < 4; ++i) acc[mt][nt][i] = 0.f;

    uint4 pa[2], pw[2];
#pragma unroll
    for (int it = 0; it < 2; ++it) {
        int ch = tid + it * 256;
        int m = ch >> 2, kc = (ch & 3) << 3;
        pa[it] = *(const uint4*)(A + (size_t)(bm + m) * Dd + kc);
        pw[it] = *(const uint4*)(Wt + (size_t)(bn + m) * Dd + kc);
    }
#pragma unroll
    for (int it = 0; it < 2; ++it) {
        int ch = tid + it * 256;
        int m = ch >> 2, kc = (ch & 3) << 3;
        *(uint4*)&As_[m][kc] = pa[it];
        *(uint4*)&Bs_[m][kc] = pw[it];
    }
    __syncthreads();

    for (int k0 = 32; k0 <= Dd; k0 += 32) {
        if (k0 < Dd) {
#pragma unroll
            for (int it = 0; it < 2; ++it) {
                int ch = tid + it * 256;
                int m = ch >> 2, kc = (ch & 3) << 3;
                pa[it] = *(const uint4*)(A + (size_t)(bm + m) * Dd + k0 + kc);
                pw[it] = *(const uint4*)(Wt + (size_t)(bn + m) * Dd + k0 + kc);
            }
        }
#pragma unroll
        for (int ks = 0; ks < 32; ks += 16) {
            uint32_t af[4][4], bf[4][2];
#pragma unroll
            for (int mt = 0; mt < 4; ++mt) {
                int r = warpM + mt * 16 + g;
                af[mt][0] = *(uint32_t*)&As_[r][ks + 2*tg];
                af[mt][1] = *(uint32_t*)&As_[r + 8][ks + 2*tg];
                af[mt][2] = *(uint32_t*)&As_[r][ks + 2*tg + 8];
                af[mt][3] = *(uint32_t*)&As_[r + 8][ks + 2*tg + 8];
            }
#pragma unroll
            for (int nt = 0; nt < 4; ++nt) {
                int c = warpN + nt * 8 + g;
                bf[nt][0] = *(uint32_t*)&Bs_[c][ks + 2*tg];
                bf[nt][1] = *(uint32_t*)&Bs_[c][ks + 2*tg + 8];
            }
#pragma unroll
            for (int mt = 0; mt < 4; ++mt)
#pragma unroll
                for (int nt = 0; nt < 4; ++nt)
                    mma_f16(acc[mt][nt], af[mt], bf[nt]);
        }
        if (k0 < Dd) {
            __syncthreads();
#pragma unroll
            for (int it = 0; it < 2; ++it) {
                int ch = tid + it * 256;
                int m = ch >> 2, kc = (ch & 3) << 3;
                *(uint4*)&As_[m][kc] = pa[it];
                *(uint4*)&Bs_[m][kc] = pw[it];
            }
            __syncthreads();
        }
    }

#pragma unroll
    for (int mt = 0; mt < 4; ++mt)
#pragma unroll
        for (int nt = 0; nt < 4; ++nt) {
            int r0 = bm + warpM + mt * 16 + g;
            int c0 = bn + warpN + nt * 8 + 2 * tg;
            int b = r0 >> 11, s = r0 & 2047;
            int h = c0 >> 6, d = c0 & 63;
            float b0 = bp[c0], b1 = bp[c0 + 1];
            __half* dst = Oh + ((size_t)(b * 16 + h) * 2048 + s) * 64 + d;
            *(__half2*)(dst)          = __floats2half2_rn(acc[mt][nt][0] + b0, acc[mt][nt][1] + b1);
            *(__half2*)(dst + 8 * 64) = __floats2half2_rn(acc[mt][nt][2] + b0, acc[mt][nt][3] + b1);
        }
}

// ---------------------------------------------------------------------------
// Output projection (f16 x f16 -> fp32): out = g_A @ Wo' + bo
// ---------------------------------------------------------------------------
__global__ __launch_bounds__(256) void gemm_f16_bias(
    const __half* __restrict__ A, const __half* __restrict__ Wt,
    const float* __restrict__ bias, float* __restrict__ C)
{
    __shared__ __half As_[128][40];
    __shared__ __half Bs_[128][40];
    const int tid  = threadIdx.x;
    const int lane = tid & 31, w = tid >> 5;
    const int g = lane >> 2, tg = lane & 3;
    const int bm = blockIdx.y * 128, bn = blockIdx.x * 128;
    const int warpM = (w >> 2) * 64, warpN = (w & 3) * 32;

    float acc[4][4][4];
#pragma unroll
    for (int mt = 0; mt < 4; ++mt)
#pragma unroll
        for (int nt = 0; nt < 4; ++nt)
#pragma unroll
            for (int i = 0; i < 4; ++i) acc[mt][nt][i] = 0.f;

    uint4 pa[2], pw[2];
#pragma unroll
    for (int it = 0; it < 2; ++it) {
        int ch = tid + it * 256;
        int m = ch >> 2, kc = (ch & 3) << 3;
        pa[it] = *(const uint4*)(A + (size_t)(bm + m) * Dd + kc);
        pw[it] = *(const uint4*)(Wt + (size_t)(bn + m) * Dd + kc);
    }
#pragma unroll
    for (int it = 0; it < 2; ++it) {
        int ch = tid + it * 256;
        int m = ch >> 2, kc = (ch & 3) << 3;
        *(uint4*)&As_[m][kc] = pa[it];
        *(uint4*)&Bs_[m][kc] = pw[it];
    }
    __syncthreads();

    for (int k0 = 32; k0 <= Dd; k0 += 32) {
        if (k0 < Dd) {
#pragma unroll
            for (int it = 0; it < 2; ++it) {
                int ch = tid + it * 256;
                int m = ch >> 2, kc = (ch & 3) << 3;
                pa[it] = *(const uint4*)(A + (size_t)(bm + m) * Dd + k0 + kc);
                pw[it] = *(const uint4*)(Wt + (size_t)(bn + m) * Dd + k0 + kc);
            }
        }
#pragma unroll
        for (int ks = 0; ks < 32; ks += 16) {
            uint32_t af[4][4], bf[4][2];
#pragma unroll
            for (int mt = 0; mt < 4; ++mt) {
                int r = warpM + mt * 16 + g;
                af[mt][0] = *(uint32_t*)&As_[r][ks + 2*tg];
                af[mt][1] = *(uint32_t*)&As_[r + 8][ks + 2*tg];
                af[mt][2] = *(uint32_t*)&As_[r][ks + 2*tg + 8];
                af[mt][3] = *(uint32_t*)&As_[r + 8][ks + 2*tg + 8];
            }
#pragma unroll
            for (int nt = 0; nt < 4; ++nt) {
                int c = warpN + nt * 8 + g;
                bf[nt][0] = *(uint32_t*)&Bs_[c][ks + 2*tg];
                bf[nt][1] = *(uint32_t*)&Bs_[c][ks + 2*tg + 8];
            }
#pragma unroll
            for (int mt = 0; mt < 4; ++mt)
#pragma unroll
                for (int nt = 0; nt < 4; ++nt)
                    mma_f16(acc[mt][nt], af[mt], bf[nt]);
        }
        if (k0 < Dd) {
            __syncthreads();
#pragma unroll
            for (int it = 0; it < 2; ++it) {
                int ch = tid + it * 256;
                int m = ch >> 2, kc = (ch & 3) << 3;
                *(uint4*)&As_[m][kc] = pa[it];
                *(uint4*)&Bs_[m][kc] = pw[it];
            }
            __syncthreads();
        }
    }
#pragma unroll
    for (int mt = 0; mt < 4; ++mt)
#pragma unroll
        for (int nt = 0; nt < 4; ++nt) {
            int r0 = bm + warpM + mt * 16 + g;
            int c0 = bn + warpN + nt * 8 + 2 * tg;
            float b0 = bias[c0], b1 = bias[c0 + 1];
            float2 v0 = {acc[mt][nt][0] + b0, acc[mt][nt][1] + b1};
            float2 v1 = {acc[mt][nt][2] + b0, acc[mt][nt][3] + b1};
            *(float2*)(C + (size_t)r0 * Dd + c0) = v0;
            *(float2*)(C + (size_t)(r0 + 8) * Dd + c0) = v1;
        }
}

// ---------------------------------------------------------------------------
// Scores (f16): per plane z: Sc[l,n] = 0.125 * Qh[l,:].Kh[n,:], K=64 one-shot.
// ---------------------------------------------------------------------------
__global__ __launch_bounds__(256) void scores_f16()
{
    __shared__ __half Qs_[128][72];
    __shared__ __half Ks_[128][72];
    const int tid  = threadIdx.x;
    const int lane = tid & 31, w = tid >> 5;
    const int g = lane >> 2, tg = lane & 3;
    const int z  = blockIdx.z;
    const int bm = blockIdx.y * 128, bn = blockIdx.x * 128;
    const int warpM = (w >> 2) * 64, warpN = (w & 3) * 32;
    const __half* Q  = g_Qh + (size_t)z * (Ss*HDd);
    const __half* Kp = g_Kh + (size_t)z * (Ss*HDd);

    float acc[4][4][4];
#pragma unroll
    for (int mt = 0; mt < 4; ++mt)
#pragma unroll
        for (int nt = 0; nt < 4; ++nt)
#pragma unroll
            for (int i = 0; i < 4; ++i) acc[mt][nt][i] = 0.f;

#pragma unroll
    for (int it = 0; it < 4; ++it) {
        int ch = tid + it * 256;
        int s = ch >> 3, dc = (ch & 7) << 3;
        *(uint4*)&Qs_[s][dc] = *(const uint4*)(Q  + (size_t)(bm + s) * HDd + dc);
        *(uint4*)&Ks_[s][dc] = *(const uint4*)(Kp + (size_t)(bn + s) * HDd + dc);
    }
    __syncthreads();

#pragma unroll
    for (int ks = 0; ks < 64; ks += 16) {
        uint32_t af[4][4], bf[4][2];
#pragma unroll
        for (int mt = 0; mt < 4; ++mt) {
            int r = warpM + mt * 16 + g;
            af[mt][0] = *(uint32_t*)&Qs_[r][ks + 2*tg];
            af[mt][1] = *(uint32_t*)&Qs_[r + 8][ks + 2*tg];
            af[mt][2] = *(uint32_t*)&Qs_[r][ks + 2*tg + 8];
            af[mt][3] = *(uint32_t*)&Qs_[r + 8][ks + 2*tg + 8];
        }
#pragma unroll
        for (int nt = 0; nt < 4; ++nt) {
            int c = warpN + nt * 8 + g;
            bf[nt][0] = *(uint32_t*)&Ks_[c][ks + 2*tg];
            bf[nt][1] = *(uint32_t*)&Ks_[c][ks + 2*tg + 8];
        }
#pragma unroll
        for (int mt = 0; mt < 4; ++mt)
#pragma unroll
            for (int nt = 0; nt < 4; ++nt)
                mma_f16(acc[mt][nt], af[mt], bf[nt]);
    }

    __half* out = g_Sc + (size_t)z * PLANE;
#pragma unroll
    for (int mt = 0; mt < 4; ++mt)
#pragma unroll
        for (int nt = 0; nt < 4; ++nt) {
            int r0 = bm + warpM + mt * 16 + g;
            int c0 = bn + warpN + nt * 8 + 2 * tg;
            *(__half2*)(out + (size_t)r0 * Ss + c0) =
                __floats2half2_rn(0.125f*acc[mt][nt][0], 0.125f*acc[mt][nt][1]);
            *(__half2*)(out + (size_t)(r0 + 8) * Ss + c0) =
                __floats2half2_rn(0.125f*acc[mt][nt][2], 0.125f*acc[mt][nt][3]);
        }
}

// ---------------------------------------------------------------------------
// Softmax over HEAD axis, 2 consecutive n per thread (half2 traffic).
// Reads fp16 scores; writes fp32 probs (output) + fp16 P planes.
// ---------------------------------------------------------------------------
__global__ __launch_bounds__(256) void softmax_kernel(float* __restrict__ probs)
{
    int i = blockIdx.x * 256 + threadIdx.x;     // over (b,l,n/2)
    int n2 = i & 1023;
    int l  = (i >> 10) & 2047;
    int b  = i >> 21;
    int n  = n2 << 1;
    size_t off = (size_t)l * Ss + n;

    float s0[16], s1[16];
#pragma unroll
    for (int h = 0; h < 16; ++h) {
        __half2 v = *(const __half2*)(g_Sc + (size_t)(b*16 + h) * PLANE + off);
        float2 f = __half22float2(v);
        s0[h] = f.x; s1[h] = f.y;
    }

    float m0 = s0[0], m1 = s1[0];
#pragma unroll
    for (int h = 1; h < 16; ++h) { m0 = fmaxf(m0, s0[h]); m1 = fmaxf(m1, s1[h]); }
    float sum0 = 0.f, sum1 = 0.f;
#pragma unroll
    for (int h = 0; h < 16; ++h) {
        s0[h] = __expf(s0[h] - m0); sum0 += s0[h];
        s1[h] = __expf(s1[h] - m1); sum1 += s1[h];
    }
    float r0 = 1.0f / sum0, r1 = 1.0f / sum1;

    float* po = probs + ((size_t)((b * 2048 + l) * 2048 + n)) * 16;
#pragma unroll
    for (int h4 = 0; h4 < 16; h4 += 4) {
        float4 o = {s0[h4]*r0, s0[h4+1]*r0, s0[h4+2]*r0, s0[h4+3]*r0};
        *(float4*)(po + h4) = o;
    }
#pragma unroll
    for (int h4 = 0; h4 < 16; h4 += 4) {
        float4 o = {s1[h4]*r1, s1[h4+1]*r1, s1[h4+2]*r1, s1[h4+3]*r1};
        *(float4*)(po + 16 + h4) = o;
    }
#pragma unroll
    for (int h = 0; h < 16; ++h) {
        *(__half2*)(g_P + (size_t)(b*16 + h) * PLANE + off) =
            __floats2half2_rn(s0[h] * r0, s1[h] * r1);
    }
}

// ---------------------------------------------------------------------------
// Attn*V (f16): per plane z: O[l,d] = sum_n P[l,n] * V[n,d]
// BK=64, V transposed to [d][n] at smem store. Writes g_A interleaved fp16.
// ---------------------------------------------------------------------------
__global__ __launch_bounds__(256) void attnv_f16()
{
    __shared__ __half Ps_[128][72];
    __shared__ __half Vs_[64][72];
    const int tid  = threadIdx.x;
    const int lane = tid & 31, w = tid >> 5;
    const int g = lane >> 2, tg = lane & 3;
    const int z  = blockIdx.y;
    const int bm = blockIdx.x * 128;
    const int warpM = (w >> 1) * 32, warpN = (w & 1) * 32;
    const __half* P = g_P + (size_t)z * PLANE;
    const __half* V = g_Vh + (size_t)z * (Ss*HDd);
    const int bz = z >> 4, hz = z & 15;
    __half* O = g_A + ((size_t)bz * 2048) * 1024 + hz * 64;

    float acc[2][4][4];
#pragma unroll
    for (int mt = 0; mt < 2; ++mt)
#pragma unroll
        for (int nt = 0; nt < 4; ++nt)
#pragma unroll
            for (int i = 0; i < 4; ++i) acc[mt][nt][i] = 0.f;

    uint4 pp[4], pv[2];
    {
#pragma unroll
        for (int it = 0; it < 4; ++it) {
            int ch = tid + it * 256;
            int m = ch >> 3, kc = (ch & 7) << 3;
            pp[it] = *(const uint4*)(P + (size_t)(bm + m) * Ss + kc);
        }
#pragma unroll
        for (int it = 0; it < 2; ++it) {
            int ch = tid + it * 256;
            int vn = ch >> 3, vdc = (ch & 7) << 3;
            pv[it] = *(const uint4*)(V + (size_t)vn * HDd + vdc);
        }
    }
#pragma unroll
    for (int it = 0; it < 4; ++it) {
        int ch = tid + it * 256;
        int m = ch >> 3, kc = (ch & 7) << 3;
        *(uint4*)&Ps_[m][kc] = pp[it];
    }
#pragma unroll
    for (int it = 0; it < 2; ++it) {
        int ch = tid + it * 256;
        int vn = ch >> 3, vdc = (ch & 7) << 3;
        H8 t; t.u = pv[it];
#pragma unroll
        for (int j = 0; j < 8; ++j) Vs_[vdc + j][vn] = t.h[j];
    }
    __syncthreads();

    for (int k0 = 64; k0 <= Ss; k0 += 64) {
        if (k0 < Ss) {
#pragma unroll
            for (int it = 0; it < 4; ++it) {
                int ch = tid + it * 256;
                int m = ch >> 3, kc = (ch & 7) << 3;
                pp[it] = *(const uint4*)(P + (size_t)(bm + m) * Ss + k0 + kc);
            }
#pragma unroll
            for (int it = 0; it < 2; ++it) {
                int ch = tid + it * 256;
                int vn = ch >> 3, vdc = (ch & 7) << 3;
                pv[it] = *(const uint4*)(V + (size_t)(k0 + vn) * HDd + vdc);
            }
        }
#pragma unroll
        for (int ks = 0; ks < 64; ks += 16) {
            uint32_t af[2][4], bf[4][2];
#pragma unroll
            for (int mt = 0; mt < 2; ++mt) {
                int r = warpM + mt * 16 + g;
                af[mt][0] = *(uint32_t*)&Ps_[r][ks + 2*tg];
                af[mt][1] = *(uint32_t*)&Ps_[r + 8][ks + 2*tg];
                af[mt][2] = *(uint32_t*)&Ps_[r][ks + 2*tg + 8];
                af[mt][3] = *(uint32_t*)&Ps_[r + 8][ks + 2*tg + 8];
            }
#pragma unroll
            for (int nt = 0; nt < 4; ++nt) {
                int c = warpN + nt * 8 + g;
                bf[nt][0] = *(uint32_t*)&Vs_[c][ks + 2*tg];
                bf[nt][1] = *(uint32_t*)&Vs_[c][ks + 2*tg + 8];
            }
#pragma unroll
            for (int mt = 0; mt < 2; ++mt)
#pragma unroll
                for (int nt = 0; nt < 4; ++nt)
                    mma_f16(acc[mt][nt], af[mt], bf[nt]);
        }
        if (k0 < Ss) {
            __syncthreads();
#pragma unroll
            for (int it = 0; it < 4; ++it) {
                int ch = tid + it * 256;
                int m = ch >> 3, kc = (ch & 7) << 3;
                *(uint4*)&Ps_[m][kc] = pp[it];
            }
#pragma unroll
            for (int it = 0; it < 2; ++it) {
                int ch = tid + it * 256;
                int vn = ch >> 3, vdc = (ch & 7) << 3;
                H8 t; t.u = pv[it];
#pragma unroll
                for (int j = 0; j < 8; ++j) Vs_[vdc + j][vn] = t.h[j];
            }
            __syncthreads();
        }
    }
#pragma unroll
    for (int mt = 0; mt < 2; ++mt)
#pragma unroll
        for (int nt = 0; nt < 4; ++nt) {
            int r0 = bm + warpM + mt * 16 + g;
            int c0 = warpN + nt * 8 + 2 * tg;
            *(__half2*)(O + (size_t)r0 * 1024 + c0) =
                __floats2half2_rn(acc[mt][nt][0], acc[mt][nt][1]);
            *(__half2*)(O + (size_t)(r0 + 8) * 1024 + c0) =
                __floats2half2_rn(acc[mt][nt][2], acc[mt][nt][3]);
        }
}

// ---------------------------------------------------------------------------
extern "C" void kernel_launch(void* const* d_in, const int* in_sizes, int n_in,
                              void* d_out, int out_size)
{
    const float* query = (const float*)d_in[0];
    const float* key   = (const float*)d_in[1];
    const float* value = (const float*)d_in[2];
    const float* Wq = (const float*)d_in[3];  const float* bq = (const float*)d_in[4];
    const float* Wk = (const float*)d_in[5];  const float* bk = (const float*)d_in[6];
    const float* Wv = (const float*)d_in[7];  const float* bv = (const float*)d_in[8];
    const float* Wo = (const float*)d_in[9];  const float* bo = (const float*)d_in[10];

    float* out   = (float*)d_out;
    float* probs = out + BSD;

    void* p;
    cudaGetSymbolAddress(&p, g_Wq); __half* gWq = (__half*)p;
    cudaGetSymbolAddress(&p, g_Wk); __half* gWk = (__half*)p;
    cudaGetSymbolAddress(&p, g_Wv); __half* gWv = (__half*)p;
    cudaGetSymbolAddress(&p, g_Wo); __half* gWo = (__half*)p;
    cudaGetSymbolAddress(&p, g_bp); float*  gbp = (float*)p;
    cudaGetSymbolAddress(&p, g_X);  __half* gX  = (__half*)p;
    cudaGetSymbolAddress(&p, g_Qh); __half* gQh = (__half*)p;
    cudaGetSymbolAddress(&p, g_Kh); __half* gKh = (__half*)p;
    cudaGetSymbolAddress(&p, g_Vh); __half* gVh = (__half*)p;
    cudaGetSymbolAddress(&p, g_A);  __half* gA  = (__half*)p;

    dim3 gemm_grid(Dd/128, MM/128);   // (8, 32)

    // 0) Weight/bias permutations + input fp16 conversion
    perm_wT<<<64, 256>>>(Wq, gWq);
    perm_wT<<<64, 256>>>(Wk, gWk);
    perm_wT<<<64, 256>>>(Wv, gWv);
    perm_woT<<<64, 256>>>(Wo, gWo);
    perm_bias<<<12, 256>>>(bq, bk, bv, gbp);
    conv_f16<<<BSD/2048, 256>>>(query, gX);
    conv_f16<<<BSD/2048, 256>>>(key,   gX + BSD);
    conv_f16<<<BSD/2048, 256>>>(value, gX + 2*BSD);

    // 1) Projections (all-fp16) -> fp16 head layout
    gemm_f16_headout<<<gemm_grid, 256>>>(gX,         gWq, gbp,        gQh);
    gemm_f16_headout<<<gemm_grid, 256>>>(gX + BSD,   gWk, gbp + 1024, gKh);
    gemm_f16_headout<<<gemm_grid, 256>>>(gX + 2*BSD, gWv, gbp + 2048, gVh);

    // 2) Per-head raw scores (fp16) into g_Sc
    scores_f16<<<dim3(Ss/128, Ss/128, Bb*NHh), 256>>>();

    // 3) Softmax over heads (2 n/thread): fp32 probs output + fp16 P planes
    softmax_kernel<<<(Bb*(size_t)Ss*Ss/2)/256, 256>>>(probs);

    // 4) Attn*V (fp16, BK=64) -> interleaved fp16 activations
    attnv_f16<<<dim3(Ss/128, Bb*NHh), 256>>>();

    // 5) Output projection (fp16 inputs, fp32 out)
    gemm_f16_bias<<<gemm_grid, 256>>>(gA, gWo, bo, out);
}